// round 13
// baseline (speedup 1.0000x reference)
#include <cuda_runtime.h>
#include <cuda_bf16.h>
#include <cstdint>
#include <math.h>

#define B_ 128
#define N_ 784
#define C_ 512
#define K_ 64
#define APAD 72      // padded row length (bf16) for conflict-free ldmatrix

// ---------------- scratch (no allocations allowed) -------------------------
__device__ __align__(16) __nv_bfloat16 g_an_bf16[8][K_][APAD];   // per-chunk anchor tiles

__device__ __forceinline__ uint32_t smem_u32(const void* p) {
    uint32_t a;
    asm("{ .reg .u64 t; cvta.to.shared.u64 t, %1; cvt.u32.u64 %0, t; }" : "=r"(a) : "l"(p));
    return a;
}

#define LDSM4(r0, r1, r2, r3, addr) \
    asm volatile("ldmatrix.sync.aligned.m8n8.x4.shared.b16 {%0,%1,%2,%3}, [%4];" \
                 : "=r"(r0), "=r"(r1), "=r"(r2), "=r"(r3) : "r"(addr))

__device__ __forceinline__ void mma_bf16(float d[4], const uint32_t a[4],
                                         uint32_t b0, uint32_t b1) {
    asm volatile(
        "mma.sync.aligned.m16n8k16.row.col.f32.bf16.bf16.f32 "
        "{%0,%1,%2,%3}, {%4,%5,%6,%7}, {%8,%9}, {%0,%1,%2,%3};"
        : "+f"(d[0]), "+f"(d[1]), "+f"(d[2]), "+f"(d[3])
        : "r"(a[0]), "r"(a[1]), "r"(a[2]), "r"(a[3]), "r"(b0), "r"(b1));
}

__device__ __forceinline__ float sigmoidf_(float t) {
    if (t >= 0.f) { float e = __expf(-t); return 1.f / (1.f + e); }
    float e = __expf(t); return e / (1.f + e);
}

// ---------------------------------------------------------------------------
// Kernel 1: normalize anchors -> bf16 per-chunk padded tiles. grid=64, blk=128.
// ---------------------------------------------------------------------------
__global__ void __launch_bounds__(128) anchor_kernel(const float* __restrict__ kern) {
    int k = blockIdx.x;
    int tid = threadIdx.x;
    __shared__ float red[4];
    float s = 0.f;
    for (int c = tid; c < C_; c += 128) { float v = kern[k * C_ + c]; s += v * v; }
#pragma unroll
    for (int o = 16; o; o >>= 1) s += __shfl_xor_sync(0xffffffffu, s, o);
    if ((tid & 31) == 0) red[tid >> 5] = s;
    __syncthreads();
    float inv = 1.f / (sqrtf(red[0] + red[1] + red[2] + red[3]) + 1e-12f);
    for (int p = tid; p < 256; p += 128) {
        int c = p * 2;
        int kc = c >> 6, cc = c & 63;
        __nv_bfloat162 h = __floats2bfloat162_rn(kern[k * C_ + c] * inv,
                                                 kern[k * C_ + c + 1] * inv);
        *reinterpret_cast<__nv_bfloat162*>(&g_an_bf16[kc][k][cc]) = h;
    }
}

// ---------------------------------------------------------------------------
// Fused kernel: one block per batch (grid=128, single wave), 256 threads.
// Phase 1: GEMM [784x512]x[512x64] in 7 row-tiles of 112 (warps 0-6 MMA),
//          anchors resident in smem, double-buffered A tiles, raw prefetch.
// Then in-block vsolve (10 iters), then phase 2: weighted mean re-reading the
// batch's 1.6MB in REVERSE order (L2 hits on phase-1 tail). Output direct.
//
// smem map (bytes):
//   SA_ALL  @0       73728   anchors [8][64][72] bf16 (persistent)
//   A0      @73728   16128   A tile 112x72 bf16
//   A1      @89856   16128
//   SNP     @105984   7168   norm partials [16][112] f32  (phase2: cbuf 2048)
//   SINV    @113152    448
//   SLS     @113600   3136   logS -> weights (in place)
//   RED     @116736     32
//   VSH     @116768      4
// ---------------------------------------------------------------------------
#define SA_ALL 0u
#define PH_A0  73728u
#define PH_A1  89856u
#define PH_SNP 105984u
#define PH_SINV 113152u
#define PH_SLS 113600u
#define PH_RED 116736u
#define PH_VSH 116768u
#define SMEM_TOTAL 116800

__global__ void __launch_bounds__(256) fused_kernel(const float* __restrict__ x,
                                                    float* __restrict__ out) {
    extern __shared__ __align__(16) char smem[];
    const uint32_t sb = smem_u32(smem);
    const int tid = threadIdx.x;
    const int lane = tid & 31, wid = tid >> 5;
    const int seg = tid & 15, rowq = tid >> 4;
    const int b = blockIdx.x;

    // ldmatrix per-lane address components
    const uint32_t a_rowl = (uint32_t)(wid * 16 + (lane & 15));     // tile-local row
    const uint32_t a_colb = (uint32_t)((lane >> 4) << 3);
    const uint32_t b_rowo = (uint32_t)((lane & 7) + ((lane >> 4) << 3));
    const uint32_t b_colo = (uint32_t)(lane & 8);

    const float* xg = x + (size_t)b * N_ * C_;

    // load anchors into smem once (73728 B = 4608 uint4)
    {
        const uint4* src = reinterpret_cast<const uint4*>(g_an_bf16);
#pragma unroll
        for (int i = 0; i < 18; i++)
            reinterpret_cast<uint4*>(smem)[tid + 256 * i] = src[tid + 256 * i];
    }
    // (first use of B is after the sync that follows stage(0))

    float acc[8][4];
#pragma unroll
    for (int t = 0; t < 8; t++)
#pragma unroll
        for (int i = 0; i < 4; i++) acc[t][i] = 0.f;
    float nsqr[7];
#pragma unroll
    for (int j = 0; j < 7; j++) nsqr[j] = 0.f;

    float4 rx[7];   // RAW prefetched floats, no consumer until stage

    auto prefetch = [&](int ci) {
        const int rowbase = (ci >> 3) * 112;
        const int kcol = (ci & 7) * 64;
#pragma unroll
        for (int j = 0; j < 7; j++)
            rx[j] = *reinterpret_cast<const float4*>(
                xg + (size_t)(rowbase + rowq + 16 * j) * C_ + kcol + seg * 4);
    };
    auto stage = [&](uint32_t aoff) {
#pragma unroll
        for (int j = 0; j < 7; j++) {
            float4 v = rx[j];
            nsqr[j] += v.x * v.x + v.y * v.y + v.z * v.z + v.w * v.w;
            __nv_bfloat162 h0 = __floats2bfloat162_rn(v.x, v.y);
            __nv_bfloat162 h1 = __floats2bfloat162_rn(v.z, v.w);
            uint32_t u0 = *reinterpret_cast<uint32_t*>(&h0);
            uint32_t u1 = *reinterpret_cast<uint32_t*>(&h1);
            uint32_t off = aoff + (uint32_t)((rowq + 16 * j) * (APAD * 2) + seg * 8);
            asm volatile("st.shared.v2.b32 [%0], {%1,%2};"
                         :: "r"(sb + off), "r"(u0), "r"(u1) : "memory");
        }
    };

    prefetch(0);

#pragma unroll 1
    for (int ci = 0; ci < 56; ci++) {
        const uint32_t aoff = (ci & 1) ? PH_A1 : PH_A0;
        const int kc = ci & 7;
        stage(aoff);
        __syncthreads();
        if (ci < 55) prefetch(ci + 1);   // LDGs overlap MMA below

        if (wid < 7) {
#pragma unroll
            for (int ks = 0; ks < 4; ks++) {
                uint32_t a[4];
                LDSM4(a[0], a[1], a[2], a[3],
                      sb + aoff + a_rowl * (APAD * 2) + (ks * 16 + a_colb) * 2);
#pragma unroll
                for (int nt = 0; nt < 4; nt++) {
                    uint32_t b0, b1, b2, b3;
                    LDSM4(b0, b1, b2, b3,
                          sb + SA_ALL + (uint32_t)kc * 9216u
                             + (nt * 16 + b_rowo) * (APAD * 2) + (ks * 16 + b_colo) * 2);
                    mma_bf16(acc[2 * nt], a, b0, b1);
                    mma_bf16(acc[2 * nt + 1], a, b2, b3);
                }
            }
        }

        if (kc == 7) {                 // tile epilogue (uniform branch)
            const int rt = ci >> 3;
            float* snp = reinterpret_cast<float*>(smem + PH_SNP);   // [16][112]
#pragma unroll
            for (int j = 0; j < 7; j++) { snp[seg * 112 + rowq + 16 * j] = nsqr[j]; nsqr[j] = 0.f; }
            __syncthreads();
            float* sinv = reinterpret_cast<float*>(smem + PH_SINV);
            if (tid < 112) {
                float s2 = 0.f;
#pragma unroll
                for (int j2 = 0; j2 < 16; j2++) s2 += snp[j2 * 112 + tid];
                sinv[tid] = 20.f / (sqrtf(s2) + 1e-12f);
            }
            __syncthreads();
            if (wid < 7) {
                const int g = lane >> 2;
                const int lr0 = wid * 16 + g, lr1 = lr0 + 8;
                const float i0 = sinv[lr0], i1 = sinv[lr1];
                float p0 = 0.f, p1 = 0.f;
#pragma unroll
                for (int t = 0; t < 8; t++) {
                    p0 += __expf(fmaf(i0, acc[t][0], -20.f)) + __expf(fmaf(i0, acc[t][1], -20.f));
                    p1 += __expf(fmaf(i1, acc[t][2], -20.f)) + __expf(fmaf(i1, acc[t][3], -20.f));
                }
                p0 += __shfl_xor_sync(0xffffffffu, p0, 1);
                p0 += __shfl_xor_sync(0xffffffffu, p0, 2);
                p1 += __shfl_xor_sync(0xffffffffu, p1, 1);
                p1 += __shfl_xor_sync(0xffffffffu, p1, 2);
                if ((lane & 3) == 0) {
                    float* sls = reinterpret_cast<float*>(smem + PH_SLS);
                    sls[rt * 112 + lr0] = __logf(p0);
                    sls[rt * 112 + lr1] = __logf(p1);
                }
            }
#pragma unroll
            for (int t = 0; t < 8; t++)
#pragma unroll
                for (int i2 = 0; i2 < 4; i2++) acc[t][i2] = 0.f;
        }
    }
    __syncthreads();    // all logS in smem

    // -------- in-block vsolve (10 iterations) --------
    float* sls = reinterpret_cast<float*>(smem + PH_SLS);
    float* red = reinterpret_cast<float*>(smem + PH_RED);
    float* vshp = reinterpret_cast<float*>(smem + PH_VSH);
    float v = 0.f;
    const float logmu = logf(0.5f);
    const float logn = logf((float)N_);
    for (int it = 0; it < 10; ++it) {
        float part = 0.f;
        for (int n = tid; n < N_; n += 256) part += sigmoidf_(sls[n] + 10.f * v);
#pragma unroll
        for (int o = 16; o; o >>= 1) part += __shfl_xor_sync(0xffffffffu, part, o);
        if (lane == 0) red[wid] = part;
        __syncthreads();
        if (tid == 0) {
            float s = 0.f;
#pragma unroll
            for (int j = 0; j < 8; j++) s += red[j];
            vshp[0] = v + 0.1f * (logmu - (__logf(s) - logn));
        }
        __syncthreads();
        v = vshp[0];
    }
    // weights in place
    for (int n = tid; n < N_; n += 256) sls[n] = 2.f * sigmoidf_(sls[n] + 10.f * v);
    __syncthreads();

    // -------- phase 2: weighted mean, reverse n order for L2 reuse --------
    const int col4 = tid & 127;
    const int half = tid >> 7;
    const int nhi = half ? 392 : 784;     // descending from nhi-1
    const float4* xb4 = reinterpret_cast<const float4*>(xg);

    float4 a7[7];
#pragma unroll
    for (int j = 0; j < 7; j++) a7[j] = make_float4(0.f, 0.f, 0.f, 0.f);

#pragma unroll 1
    for (int i = 0; i < 392; i += 14) {   // 392 = 28*14
        float4 vv[14];
        float mm[14];
#pragma unroll
        for (int j = 0; j < 14; j++)
            vv[j] = xb4[(size_t)(nhi - 1 - (i + j)) * 128 + col4];
#pragma unroll
        for (int j = 0; j < 14; j++) mm[j] = sls[nhi - 1 - (i + j)];
#pragma unroll
        for (int j = 0; j < 7; j++) {
            a7[j].x += mm[j] * vv[j].x; a7[j].y += mm[j] * vv[j].y;
            a7[j].z += mm[j] * vv[j].z; a7[j].w += mm[j] * vv[j].w;
        }
#pragma unroll
        for (int j = 0; j < 7; j++) {
            a7[j].x += mm[j + 7] * vv[j + 7].x; a7[j].y += mm[j + 7] * vv[j + 7].y;
            a7[j].z += mm[j + 7] * vv[j + 7].z; a7[j].w += mm[j + 7] * vv[j + 7].w;
        }
    }
    float4 t;
    t.x = ((a7[0].x + a7[1].x) + (a7[2].x + a7[3].x)) + ((a7[4].x + a7[5].x) + a7[6].x);
    t.y = ((a7[0].y + a7[1].y) + (a7[2].y + a7[3].y)) + ((a7[4].y + a7[5].y) + a7[6].y);
    t.z = ((a7[0].z + a7[1].z) + (a7[2].z + a7[3].z)) + ((a7[4].z + a7[5].z) + a7[6].z);
    t.w = ((a7[0].w + a7[1].w) + (a7[2].w + a7[3].w)) + ((a7[4].w + a7[5].w) + a7[6].w);

    float4* cbuf = reinterpret_cast<float4*>(smem + PH_SNP);
    if (half == 1) cbuf[col4] = t;
    __syncthreads();
    if (half == 0) {
        float4 o = cbuf[col4];
        const float inv = 1.f / (float)N_;
        o.x = (o.x + t.x) * inv;
        o.y = (o.y + t.y) * inv;
        o.z = (o.z + t.z) * inv;
        o.w = (o.w + t.w) * inv;
        reinterpret_cast<float4*>(out + (size_t)b * C_)[col4] = o;
    }
}

// ---------------------------------------------------------------------------
extern "C" void kernel_launch(void* const* d_in, const int* in_sizes, int n_in,
                              void* d_out, int out_size) {
    const float* bow = (const float*)d_in[0];
    const float* kern = (const float*)d_in[1];
    if (n_in >= 2 && in_sizes[0] < in_sizes[1]) {  // defensive: pick by size
        const float* t = bow; bow = kern; kern = t;
    }
    static bool attr_set = false;
    if (!attr_set) {
        cudaFuncSetAttribute(fused_kernel, cudaFuncAttributeMaxDynamicSharedMemorySize,
                             SMEM_TOTAL);
        attr_set = true;
    }
    anchor_kernel<<<K_, 128>>>(kern);
    fused_kernel<<<B_, 256, SMEM_TOTAL>>>(bow, (float*)d_out);
}

// round 14
// speedup vs baseline: 1.1535x; 1.1535x over previous
#include <cuda_runtime.h>
#include <cuda_bf16.h>
#include <cstdint>
#include <math.h>

#define B_ 128
#define N_ 784
#define C_ 512
#define K_ 64
#define APAD 72      // padded row length (bf16) for conflict-free ldmatrix

// ---------------- scratch (no allocations allowed) -------------------------
__device__ __align__(16) __nv_bfloat16 g_an_bf16[8][K_][APAD];   // per-chunk anchor tiles

__device__ __forceinline__ uint32_t smem_u32(const void* p) {
    uint32_t a;
    asm("{ .reg .u64 t; cvta.to.shared.u64 t, %1; cvt.u32.u64 %0, t; }" : "=r"(a) : "l"(p));
    return a;
}

#define LDSM4(r0, r1, r2, r3, addr) \
    asm volatile("ldmatrix.sync.aligned.m8n8.x4.shared.b16 {%0,%1,%2,%3}, [%4];" \
                 : "=r"(r0), "=r"(r1), "=r"(r2), "=r"(r3) : "r"(addr))

#define HBAR(id) \
    asm volatile("bar.sync %0, 256;" :: "r"(id) : "memory")

__device__ __forceinline__ void mma_bf16(float d[4], const uint32_t a[4],
                                         uint32_t b0, uint32_t b1) {
    asm volatile(
        "mma.sync.aligned.m16n8k16.row.col.f32.bf16.bf16.f32 "
        "{%0,%1,%2,%3}, {%4,%5,%6,%7}, {%8,%9}, {%0,%1,%2,%3};"
        : "+f"(d[0]), "+f"(d[1]), "+f"(d[2]), "+f"(d[3])
        : "r"(a[0]), "r"(a[1]), "r"(a[2]), "r"(a[3]), "r"(b0), "r"(b1));
}

__device__ __forceinline__ float sigmoidf_(float t) {
    if (t >= 0.f) { float e = __expf(-t); return 1.f / (1.f + e); }
    float e = __expf(t); return e / (1.f + e);
}

// ---------------------------------------------------------------------------
// Kernel 1: normalize anchors -> bf16 per-chunk padded tiles. grid=64, blk=128.
// ---------------------------------------------------------------------------
__global__ void __launch_bounds__(128) anchor_kernel(const float* __restrict__ kern) {
    int k = blockIdx.x;
    int tid = threadIdx.x;
    __shared__ float red[4];
    float s = 0.f;
    for (int c = tid; c < C_; c += 128) { float v = kern[k * C_ + c]; s += v * v; }
#pragma unroll
    for (int o = 16; o; o >>= 1) s += __shfl_xor_sync(0xffffffffu, s, o);
    if ((tid & 31) == 0) red[tid >> 5] = s;
    __syncthreads();
    float inv = 1.f / (sqrtf(red[0] + red[1] + red[2] + red[3]) + 1e-12f);
    for (int p = tid; p < 256; p += 128) {
        int c = p * 2;
        int kc = c >> 6, cc = c & 63;
        __nv_bfloat162 h = __floats2bfloat162_rn(kern[k * C_ + c] * inv,
                                                 kern[k * C_ + c + 1] * inv);
        *reinterpret_cast<__nv_bfloat162*>(&g_an_bf16[kc][k][cc]) = h;
    }
}

// ---------------------------------------------------------------------------
// Fused kernel: one block per batch (grid=128), 512 threads = TWO independent
// 256-thread half-pipelines on half-scoped named barriers.
//   half 0 (warps 0-7):  row tiles 0-3  (rows   0-447)
//   half 1 (warps 8-15): row tiles 4-6  (rows 448-783)
// Each half: 112-row tile GEMM vs 64 anchors (warps l0-l6 MMA), double-buffered
// A tiles, raw register prefetch. Anchors resident in smem (shared by halves).
// Then full-block vsolve (10 iters) and 4-way-split weighted-mean phase 2.
//
// smem map (bytes):
//   SA_ALL @0       73728   anchors [8][64][72] bf16
//   A00    @73728   16128   half0 A buf0 (112x72 bf16)
//   A01    @89856   16128   half0 A buf1
//   A10    @105984  16128   half1 A buf0
//   A11    @122112  16128   half1 A buf1
//   SNP0   @138240   7168   half0 norm partials [16][112]  (phase2: cbuf 6144)
//   SNP1   @145408   7168   half1 norm partials
//   SINV0  @152576    448
//   SINV1  @153024    448
//   SLS    @153472   3136   logS -> weights (in place)
//   RED    @156608     64
//   VSH    @156672      4
// ---------------------------------------------------------------------------
#define SA_ALL  0u
#define PH_A00  73728u
#define PH_A01  89856u
#define PH_A10  105984u
#define PH_A11  122112u
#define PH_SNP0 138240u
#define PH_SNP1 145408u
#define PH_SINV0 152576u
#define PH_SINV1 153024u
#define PH_SLS  153472u
#define PH_RED  156608u
#define PH_VSH  156672u
#define SMEM_TOTAL 156736

__global__ void __launch_bounds__(512) fused_kernel(const float* __restrict__ x,
                                                    float* __restrict__ out) {
    extern __shared__ __align__(16) char smem[];
    const uint32_t sb = smem_u32(smem);
    const int tid = threadIdx.x;
    const int lane = tid & 31, wid = tid >> 5;
    const int half = tid >> 8;              // 0 or 1
    const int ltid = tid & 255;             // local tid within half
    const int lwid = wid & 7;               // local warp id
    const int seg = ltid & 15, rowq = ltid >> 4;
    const int barid = 1 + half;
    const int b = blockIdx.x;

    // half-dependent constants
    const int tilebase = half ? 4 : 0;
    const int nci = half ? 24 : 32;         // chunks = tiles*8
    const uint32_t aB0 = half ? PH_A10 : PH_A00;
    const uint32_t aB1 = half ? PH_A11 : PH_A01;
    const uint32_t snpo = half ? PH_SNP1 : PH_SNP0;
    const uint32_t sinvo = half ? PH_SINV1 : PH_SINV0;

    // ldmatrix per-lane address components
    const uint32_t a_rowl = (uint32_t)(lwid * 16 + (lane & 15));
    const uint32_t a_colb = (uint32_t)((lane >> 4) << 3);
    const uint32_t b_rowo = (uint32_t)((lane & 7) + ((lane >> 4) << 3));
    const uint32_t b_colo = (uint32_t)(lane & 8);

    const float* xg = x + (size_t)b * N_ * C_;

    // load anchors into smem once (4608 uint4 over 512 threads = 9 each)
    {
        const uint4* src = reinterpret_cast<const uint4*>(g_an_bf16);
#pragma unroll
        for (int i = 0; i < 9; i++)
            reinterpret_cast<uint4*>(smem)[tid + 512 * i] = src[tid + 512 * i];
    }

    float acc[8][4];
#pragma unroll
    for (int t = 0; t < 8; t++)
#pragma unroll
        for (int i = 0; i < 4; i++) acc[t][i] = 0.f;
    float nsqr[7];
#pragma unroll
    for (int j = 0; j < 7; j++) nsqr[j] = 0.f;

    float4 rx[7];   // RAW prefetched floats (no consumer until stage)

    auto prefetch = [&](int ci) {
        const int rowbase = (tilebase + (ci >> 3)) * 112;
        const int kcol = (ci & 7) * 64;
#pragma unroll
        for (int j = 0; j < 7; j++)
            rx[j] = *reinterpret_cast<const float4*>(
                xg + (size_t)(rowbase + rowq + 16 * j) * C_ + kcol + seg * 4);
    };
    auto stage = [&](uint32_t aoff) {
#pragma unroll
        for (int j = 0; j < 7; j++) {
            float4 v = rx[j];
            nsqr[j] += v.x * v.x + v.y * v.y + v.z * v.z + v.w * v.w;
            __nv_bfloat162 h0 = __floats2bfloat162_rn(v.x, v.y);
            __nv_bfloat162 h1 = __floats2bfloat162_rn(v.z, v.w);
            uint32_t u0 = *reinterpret_cast<uint32_t*>(&h0);
            uint32_t u1 = *reinterpret_cast<uint32_t*>(&h1);
            uint32_t off = aoff + (uint32_t)((rowq + 16 * j) * (APAD * 2) + seg * 8);
            asm volatile("st.shared.v2.b32 [%0], {%1,%2};"
                         :: "r"(sb + off), "r"(u0), "r"(u1) : "memory");
        }
    };

    prefetch(0);
    __syncthreads();    // anchors visible to both halves before MMA

#pragma unroll 1
    for (int ci = 0; ci < nci; ci++) {
        const uint32_t aoff = (ci & 1) ? aB1 : aB0;
        const int kc = ci & 7;
        stage(aoff);
        HBAR(barid);
        if (ci < nci - 1) prefetch(ci + 1);   // LDGs overlap MMA below

        if (lwid < 7) {
#pragma unroll
            for (int ks = 0; ks < 4; ks++) {
                uint32_t a[4];
                LDSM4(a[0], a[1], a[2], a[3],
                      sb + aoff + a_rowl * (APAD * 2) + (ks * 16 + a_colb) * 2);
#pragma unroll
                for (int nt = 0; nt < 4; nt++) {
                    uint32_t b0, b1, b2, b3;
                    LDSM4(b0, b1, b2, b3,
                          sb + SA_ALL + (uint32_t)kc * 9216u
                             + (nt * 16 + b_rowo) * (APAD * 2) + (ks * 16 + b_colo) * 2);
                    mma_bf16(acc[2 * nt], a, b0, b1);
                    mma_bf16(acc[2 * nt + 1], a, b2, b3);
                }
            }
        }

        if (kc == 7) {                 // tile epilogue (uniform per half)
            const int rt = tilebase + (ci >> 3);
            float* snp = reinterpret_cast<float*>(smem + snpo);    // [16][112]
#pragma unroll
            for (int j = 0; j < 7; j++) { snp[seg * 112 + rowq + 16 * j] = nsqr[j]; nsqr[j] = 0.f; }
            HBAR(barid);
            float* sinv = reinterpret_cast<float*>(smem + sinvo);
            if (ltid < 112) {
                float s2 = 0.f;
#pragma unroll
                for (int j2 = 0; j2 < 16; j2++) s2 += snp[j2 * 112 + ltid];
                sinv[ltid] = 20.f / (sqrtf(s2) + 1e-12f);
            }
            HBAR(barid);
            if (lwid < 7) {
                const int g = lane >> 2;
                const int lr0 = lwid * 16 + g, lr1 = lr0 + 8;
                const float i0 = sinv[lr0], i1 = sinv[lr1];
                float p0 = 0.f, p1 = 0.f;
#pragma unroll
                for (int t = 0; t < 8; t++) {
                    p0 += __expf(fmaf(i0, acc[t][0], -20.f)) + __expf(fmaf(i0, acc[t][1], -20.f));
                    p1 += __expf(fmaf(i1, acc[t][2], -20.f)) + __expf(fmaf(i1, acc[t][3], -20.f));
                }
                p0 += __shfl_xor_sync(0xffffffffu, p0, 1);
                p0 += __shfl_xor_sync(0xffffffffu, p0, 2);
                p1 += __shfl_xor_sync(0xffffffffu, p1, 1);
                p1 += __shfl_xor_sync(0xffffffffu, p1, 2);
                if ((lane & 3) == 0) {
                    float* sls = reinterpret_cast<float*>(smem + PH_SLS);
                    sls[rt * 112 + lr0] = __logf(p0);
                    sls[rt * 112 + lr1] = __logf(p1);
                }
#pragma unroll
                for (int t = 0; t < 8; t++)
#pragma unroll
                    for (int i2 = 0; i2 < 4; i2++) acc[t][i2] = 0.f;
            }
        }
    }
    __syncthreads();    // all logS in smem (both halves)

    // -------- in-block vsolve (10 iterations), 512 threads --------
    float* sls = reinterpret_cast<float*>(smem + PH_SLS);
    float* red = reinterpret_cast<float*>(smem + PH_RED);
    float* vshp = reinterpret_cast<float*>(smem + PH_VSH);
    float v = 0.f;
    const float logmu = logf(0.5f);
    const float logn = logf((float)N_);
    for (int it = 0; it < 10; ++it) {
        float part = 0.f;
        for (int n = tid; n < N_; n += 512) part += sigmoidf_(sls[n] + 10.f * v);
#pragma unroll
        for (int o = 16; o; o >>= 1) part += __shfl_xor_sync(0xffffffffu, part, o);
        if (lane == 0) red[wid] = part;
        __syncthreads();
        if (tid == 0) {
            float s = 0.f;
#pragma unroll
            for (int j = 0; j < 16; j++) s += red[j];
            vshp[0] = v + 0.1f * (logmu - (__logf(s) - logn));
        }
        __syncthreads();
        v = vshp[0];
    }
    for (int n = tid; n < N_; n += 512) sls[n] = 2.f * sigmoidf_(sls[n] + 10.f * v);
    __syncthreads();

    // -------- phase 2: weighted mean, 4-way n-split, reverse order ----------
    const int col4 = tid & 127;
    const int q = tid >> 7;                // quarter 0..3
    const int ntop = q * 196 + 195;        // descending from here
    const float4* xb4 = reinterpret_cast<const float4*>(xg);

    float4 a7[7];
#pragma unroll
    for (int j = 0; j < 7; j++) a7[j] = make_float4(0.f, 0.f, 0.f, 0.f);

#pragma unroll 1
    for (int i = 0; i < 196; i += 14) {    // 196 = 14*14
        float4 vv[14];
        float mm[14];
#pragma unroll
        for (int j = 0; j < 14; j++)
            vv[j] = xb4[(size_t)(ntop - (i + j)) * 128 + col4];
#pragma unroll
        for (int j = 0; j < 14; j++) mm[j] = sls[ntop - (i + j)];
#pragma unroll
        for (int j = 0; j < 7; j++) {
            a7[j].x += mm[j] * vv[j].x; a7[j].y += mm[j] * vv[j].y;
            a7[j].z += mm[j] * vv[j].z; a7[j].w += mm[j] * vv[j].w;
        }
#pragma unroll
        for (int j = 0; j < 7; j++) {
            a7[j].x += mm[j + 7] * vv[j + 7].x; a7[j].y += mm[j + 7] * vv[j + 7].y;
            a7[j].z += mm[j + 7] * vv[j + 7].z; a7[j].w += mm[j + 7] * vv[j + 7].w;
        }
    }
    float4 t;
    t.x = ((a7[0].x + a7[1].x) + (a7[2].x + a7[3].x)) + ((a7[4].x + a7[5].x) + a7[6].x);
    t.y = ((a7[0].y + a7[1].y) + (a7[2].y + a7[3].y)) + ((a7[4].y + a7[5].y) + a7[6].y);
    t.z = ((a7[0].z + a7[1].z) + (a7[2].z + a7[3].z)) + ((a7[4].z + a7[5].z) + a7[6].z);
    t.w = ((a7[0].w + a7[1].w) + (a7[2].w + a7[3].w)) + ((a7[4].w + a7[5].w) + a7[6].w);

    float4* cbuf = reinterpret_cast<float4*>(smem + PH_SNP0);   // 3x128 float4
    if (q > 0) cbuf[(q - 1) * 128 + col4] = t;
    __syncthreads();
    if (q == 0) {
        const float inv = 1.f / (float)N_;
        float4 o = t;
#pragma unroll
        for (int p = 0; p < 3; p++) {
            float4 c = cbuf[p * 128 + col4];
            o.x += c.x; o.y += c.y; o.z += c.z; o.w += c.w;
        }
        o.x *= inv; o.y *= inv; o.z *= inv; o.w *= inv;
        reinterpret_cast<float4*>(out + (size_t)b * C_)[col4] = o;
    }
}

// ---------------------------------------------------------------------------
extern "C" void kernel_launch(void* const* d_in, const int* in_sizes, int n_in,
                              void* d_out, int out_size) {
    const float* bow = (const float*)d_in[0];
    const float* kern = (const float*)d_in[1];
    if (n_in >= 2 && in_sizes[0] < in_sizes[1]) {  // defensive: pick by size
        const float* t = bow; bow = kern; kern = t;
    }
    static bool attr_set = false;
    if (!attr_set) {
        cudaFuncSetAttribute(fused_kernel, cudaFuncAttributeMaxDynamicSharedMemorySize,
                             SMEM_TOTAL);
        attr_set = true;
    }
    anchor_kernel<<<K_, 128>>>(kern);
    fused_kernel<<<B_, 512, SMEM_TOTAL>>>(bow, (float*)d_out);
}